// round 17
// baseline (speedup 1.0000x reference)
#include <cuda_runtime.h>
#include <cuda_fp16.h>
#include <cstdint>
#include <math.h>

// Problem constants
#define BSZ 2
#define LSEQ 2048
#define HID 2048
#define NH 16
#define HD 128
#define MTOT (BSZ * LSEQ)          // 4096
#define SCALE 0.08838834764831845f // 1/sqrt(128)

// ---------------- scratch (no allocations allowed) ----------------
__device__ __align__(16) __half g_xh[MTOT * HID];   // 16.8 MB
__device__ __align__(16) __half g_Wqh[HID * HID];   // 8.4 MB
__device__ __align__(16) __half g_Wkh[HD * HID];
__device__ __align__(16) __half g_Wvh[HD * HID];
__device__ __align__(16) __half g_Woh[HID * HID];
__device__ __align__(16) __half g_Q[MTOT * HID];    // 16.8 MB
__device__ __align__(16) __half g_K[MTOT * HD];
__device__ __align__(16) __half g_V[MTOT * HD];
__device__ __align__(16) __half g_O[MTOT * HID];    // 16.8 MB

__device__ __forceinline__ uint32_t f16x2(float lo, float hi) {
    __half2 h = __floats2half2_rn(lo, hi);
    return *reinterpret_cast<uint32_t*>(&h);
}

__device__ __forceinline__ void mma_f16(float* c, const uint32_t* a,
                                        uint32_t b0, uint32_t b1) {
    asm volatile(
        "mma.sync.aligned.m16n8k16.row.col.f32.f16.f16.f32 "
        "{%0,%1,%2,%3}, {%4,%5,%6,%7}, {%8,%9}, {%0,%1,%2,%3};\n"
        : "+f"(c[0]), "+f"(c[1]), "+f"(c[2]), "+f"(c[3])
        : "r"(a[0]), "r"(a[1]), "r"(a[2]), "r"(a[3]), "r"(b0), "r"(b1));
}

__device__ __forceinline__ void ldsm_x4(uint32_t& r0, uint32_t& r1,
                                        uint32_t& r2, uint32_t& r3, uint32_t saddr) {
    asm volatile("ldmatrix.sync.aligned.m8n8.x4.shared.b16 {%0,%1,%2,%3}, [%4];"
                 : "=r"(r0), "=r"(r1), "=r"(r2), "=r"(r3) : "r"(saddr));
}

// ---------------- f32 -> f16 conversion (prep pass) ----------------
__global__ __launch_bounds__(256) void cvt_f2h(
    const float* __restrict__ in, __half* __restrict__ out, int n4)
{
    int i = blockIdx.x * blockDim.x + threadIdx.x;
    if (i < n4) {
        float4 v = *(const float4*)(in + (size_t)i * 4);
        *(uint2*)(out + (size_t)i * 4) =
            make_uint2(f16x2(v.x, v.y), f16x2(v.z, v.w));
    }
}

// ================= fp16 mma GEMM: C[M,N] = A[M,K] @ W[N,K]^T =================
// fp16 in/out (template). CTA 128x128, 256 thr, K chunk 32, ldmatrix fragments.
// Light register staging (uint4 x2/operand) -> fits 128-reg cap -> 2 CTAs/SM.
#define TBM 128
#define TBN 128
#define TBK 32
#define GK 2048
#define NCHUNK (GK / TBK)   // 64
#define APAD 20             // words per row (16 data + 4 pad), 80B (16B mult)
#define ATILE (TBM * APAD)
#define STAGEF (2 * ATILE)
#define GEMM_SMEM (2 * STAGEF * (int)sizeof(uint32_t))  // 40960 B

template <bool HALF_OUT>
__global__ __launch_bounds__(256, 2) void gemm_tc(
    const __half* __restrict__ A, const __half* __restrict__ W,
    void* __restrict__ Cv, int ldc)
{
    extern __shared__ uint32_t smw[];
    const int tid = threadIdx.x;
    const int lane = tid & 31;
    const int wid = tid >> 5;
    const int warp_m = (wid & 3) * 32;
    const int warp_n = (wid >> 2) * 64;
    const int gid = lane >> 2;
    const int tig = lane & 3;
    const int bm = blockIdx.y * TBM;
    const int bn = blockIdx.x * TBN;

    const int lrow = tid >> 2;           // 0..63 (+64*i)
    const int lq = (tid & 3) * 8;        // half col: 0,8,16,24

    const uint32_t smem0 = (uint32_t)__cvta_generic_to_shared(smw);
    uint32_t aoff[2];
#pragma unroll
    for (int i = 0; i < 2; i++) {
        int row = warp_m + i * 16 + (lane & 7) + ((lane & 8) ? 8 : 0);
        aoff[i] = (uint32_t)((row * APAD + ((lane >> 4) & 1) * 4) * 4);
    }
    uint32_t boff[4];
#pragma unroll
    for (int jp = 0; jp < 4; jp++) {
        int row = warp_n + jp * 16 + (lane & 7) + ((lane >> 4) & 1) * 8;
        boff[jp] = (uint32_t)((row * APAD + ((lane >> 3) & 1) * 4) * 4);
    }

    float acc[2][8][4];
#pragma unroll
    for (int i = 0; i < 2; i++)
#pragma unroll
        for (int j = 0; j < 8; j++)
#pragma unroll
            for (int q = 0; q < 4; q++) acc[i][j][q] = 0.f;

    uint4 ra[2], rb[2];

    // ---- prefetch chunk 0 ----
#pragma unroll
    for (int i = 0; i < 2; i++) {
        int row = lrow + i * 64;
        ra[i] = *(const uint4*)(A + (size_t)(bm + row) * GK + lq);
        rb[i] = *(const uint4*)(W + (size_t)(bn + row) * GK + lq);
    }
#pragma unroll
    for (int i = 0; i < 2; i++) {
        int row = lrow + i * 64;
        *(uint4*)&smw[row * APAD + (tid & 3) * 4] = ra[i];
        *(uint4*)&smw[ATILE + row * APAD + (tid & 3) * 4] = rb[i];
    }
    __syncthreads();

#pragma unroll 1
    for (int c = 0; c < NCHUNK; c++) {
        const int s = c & 1;
        const bool more = (c + 1 < NCHUNK);
        if (more) {
            const int k0 = (c + 1) * TBK;
#pragma unroll
            for (int i = 0; i < 2; i++) {
                int row = lrow + i * 64;
                ra[i] = *(const uint4*)(A + (size_t)(bm + row) * GK + k0 + lq);
                rb[i] = *(const uint4*)(W + (size_t)(bn + row) * GK + k0 + lq);
            }
        }

        const uint32_t abase = smem0 + (uint32_t)(s * STAGEF) * 4;
        const uint32_t bbase = abase + (uint32_t)ATILE * 4;
#pragma unroll
        for (int ks = 0; ks < 2; ks++) {            // 2 x k16
            const uint32_t kB = (uint32_t)(ks * 8) * 4;
            uint32_t af[2][4];
            ldsm_x4(af[0][0], af[0][1], af[0][2], af[0][3], abase + kB + aoff[0]);
            ldsm_x4(af[1][0], af[1][1], af[1][2], af[1][3], abase + kB + aoff[1]);
#pragma unroll
            for (int jp = 0; jp < 4; jp++) {
                uint32_t b0, b1, b2, b3;
                ldsm_x4(b0, b1, b2, b3, bbase + kB + boff[jp]);
                mma_f16(acc[0][2 * jp],     af[0], b0, b1);
                mma_f16(acc[1][2 * jp],     af[1], b0, b1);
                mma_f16(acc[0][2 * jp + 1], af[0], b2, b3);
                mma_f16(acc[1][2 * jp + 1], af[1], b2, b3);
            }
        }

        if (more) {
            uint32_t* Ad = &smw[(s ^ 1) * STAGEF];
            uint32_t* Bd = &smw[(s ^ 1) * STAGEF + ATILE];
#pragma unroll
            for (int i = 0; i < 2; i++) {
                int row = lrow + i * 64;
                *(uint4*)&Ad[row * APAD + (tid & 3) * 4] = ra[i];
                *(uint4*)&Bd[row * APAD + (tid & 3) * 4] = rb[i];
            }
        }
        __syncthreads();
    }

    // ---- epilogue ----
#pragma unroll
    for (int i = 0; i < 2; i++) {
        int r0 = bm + warp_m + i * 16 + gid;
#pragma unroll
        for (int j = 0; j < 8; j++) {
            int cn = bn + warp_n + j * 8 + 2 * tig;
            if (HALF_OUT) {
                __half* Ch = (__half*)Cv;
                *(uint32_t*)(Ch + (size_t)r0 * ldc + cn) =
                    f16x2(acc[i][j][0], acc[i][j][1]);
                *(uint32_t*)(Ch + (size_t)(r0 + 8) * ldc + cn) =
                    f16x2(acc[i][j][2], acc[i][j][3]);
            } else {
                float* Cf = (float*)Cv;
                *(float2*)(Cf + (size_t)r0 * ldc + cn) =
                    make_float2(acc[i][j][0], acc[i][j][1]);
                *(float2*)(Cf + (size_t)(r0 + 8) * ldc + cn) =
                    make_float2(acc[i][j][2], acc[i][j][3]);
            }
        }
    }
}

// ============== Flash attention v6 (fp16 in/out, ldmatrix, causal, MQA) ==============
#define FBM 128
#define FBN 64
#define QSTR 68    // words/row; 272B stride (16B-aligned)
#define VSTR 36    // words/row; 144B stride
#define KTILE (FBN * QSTR)   // 4352 words
#define VTILE (HD * VSTR)    // 4608 words
#define FL_QS 0
#define FL_KS (FL_QS + FBM * QSTR)
#define FL_VT (FL_KS + 2 * KTILE)
#define FL_MK (FL_VT + 2 * VTILE)
#define FLASH_SMEM ((FL_MK + 2 * FBN) * (int)sizeof(uint32_t))  // 107,520 B

__global__ __launch_bounds__(256) void flash_tc(
    const __half* __restrict__ Q, const __half* __restrict__ K,
    const __half* __restrict__ V, const int* __restrict__ mask,
    __half* __restrict__ O)
{
    extern __shared__ uint32_t fsw[];
    uint32_t* Qs = fsw + FL_QS;
    uint32_t* Ksb = fsw + FL_KS;
    uint32_t* Vtb = fsw + FL_VT;
    int* mkb = (int*)(fsw + FL_MK);

    const int m0 = (gridDim.x - 1 - blockIdx.x) * FBM;  // heavy tiles first
    const int bh = blockIdx.y;
    const int b = bh / NH;
    const int h = bh % NH;
    const int tid = threadIdx.x;
    const int lane = tid & 31;
    const int wid = tid >> 5;
    const int gid = lane >> 2;
    const int tig = lane & 3;
    const int wm = wid * 16;

    const uint32_t smem0 = (uint32_t)__cvta_generic_to_shared(fsw);
    const uint32_t qoff = smem0 + (uint32_t)(((wm + (lane & 7) + ((lane & 8) ? 8 : 0)) * QSTR
                                   + ((lane >> 4) & 1) * 4) * 4);
    uint32_t koff[4];
#pragma unroll
    for (int jp = 0; jp < 4; jp++) {
        int row = jp * 16 + (lane & 7) + ((lane >> 4) & 1) * 8;
        koff[jp] = (uint32_t)((row * QSTR + ((lane >> 3) & 1) * 4) * 4) + (uint32_t)(FL_KS * 4) + smem0;
    }
    uint32_t voff[8];
#pragma unroll
    for (int djp = 0; djp < 8; djp++) {
        int row = djp * 16 + (lane & 7) + ((lane >> 4) & 1) * 8;
        voff[djp] = (uint32_t)((row * VSTR + ((lane >> 3) & 1) * 4) * 4) + (uint32_t)(FL_VT * 4) + smem0;
    }

    // ---- Q tile (128 x 128 halves) -> smem ----
    for (int f = tid; f < FBM * 16; f += 256) {
        int row = f >> 4, q = f & 15;
        uint4 v = *(const uint4*)(Q + (size_t)(b * LSEQ + m0 + row) * HID + h * HD + q * 8);
        *(uint4*)&Qs[row * QSTR + q * 4] = v;
    }
    // ---- prologue: KV tile 0 into buffer 0 ----
    for (int f = tid; f < FBN * 16; f += 256) {
        int row = f >> 4, q = f & 15;
        uint4 v = *(const uint4*)(K + (size_t)(b * LSEQ + row) * HD + q * 8);
        *(uint4*)&Ksb[row * QSTR + q * 4] = v;
    }
    {
        __half* hV = (__half*)Vtb;
        for (int f = tid; f < FBN * 16; f += 256) {
            int row = f & 63, c8 = (f >> 6) * 8;
            uint4 v = *(const uint4*)(V + (size_t)(b * LSEQ + row) * HD + c8);
            const __half* pv = (const __half*)&v;
#pragma unroll
            for (int e = 0; e < 8; e++)
                hV[(c8 + e) * (VSTR * 2) + row] = pv[e];
        }
    }
    if (tid < FBN) mkb[tid] = mask[b * LSEQ + tid];
    __syncthreads();

    float o[16][4];
#pragma unroll
    for (int dj = 0; dj < 16; dj++)
#pragma unroll
        for (int c = 0; c < 4; c++) o[dj][c] = 0.f;
    float m_a = -1e30f, m_b = -1e30f, l_a = 0.f, l_b = 0.f;

    const int rA = m0 + wm + gid;
    const int rB = rA + 8;
    const int ntiles = m0 / FBN + FBM / FBN;

#pragma unroll 1
    for (int t = 0; t < ntiles; t++) {
        const int buf = t & 1;
        const uint32_t kbufB = (uint32_t)(buf * KTILE) * 4;
        const uint32_t vbufB = (uint32_t)(buf * VTILE) * 4;
        const int* mk = mkb + buf * FBN;
        const int n0 = t * FBN;
        const bool more = (t + 1 < ntiles);

        // ---- stage next KV tile in registers ----
        uint4 ka[4], va[4];
        int mreg = 1;
        if (more) {
            const int nn = n0 + FBN;
#pragma unroll
            for (int i = 0; i < 4; i++) {
                int f = tid + i * 256;
                int row = f >> 4, q = f & 15;
                ka[i] = *(const uint4*)(K + (size_t)(b * LSEQ + nn + row) * HD + q * 8);
            }
#pragma unroll
            for (int i = 0; i < 4; i++) {
                int f = tid + i * 256;
                int row = f & 63, c8 = (f >> 6) * 8;
                va[i] = *(const uint4*)(V + (size_t)(b * LSEQ + nn + row) * HD + c8);
            }
            if (tid < FBN) mreg = mask[b * LSEQ + nn + tid];
        }

        if (n0 <= m0 + wm + 15) {   // per-warp causal skip
            // ---- S = Q K^T ----
            float s[8][4];
#pragma unroll
            for (int j = 0; j < 8; j++)
#pragma unroll
                for (int c = 0; c < 4; c++) s[j][c] = 0.f;
#pragma unroll
            for (int kk = 0; kk < 8; kk++) {
                const uint32_t kB = (uint32_t)kk * 32;
                uint32_t a[4];
                ldsm_x4(a[0], a[1], a[2], a[3], qoff + kB);
#pragma unroll
                for (int jp = 0; jp < 4; jp++) {
                    uint32_t b0, b1, b2, b3;
                    ldsm_x4(b0, b1, b2, b3, koff[jp] + kbufB + kB);
                    mma_f16(s[2 * jp],     a, b0, b1);
                    mma_f16(s[2 * jp + 1], a, b2, b3);
                }
            }

            // ---- scale + causal + pad mask; warp-local row max ----
            float mxA = -1e30f, mxB = -1e30f;
#pragma unroll
            for (int j = 0; j < 8; j++) {
#pragma unroll
                for (int c = 0; c < 4; c++) {
                    int lcol = j * 8 + 2 * tig + (c & 1);
                    int col = n0 + lcol;
                    int r = (c < 2) ? rA : rB;
                    float v = s[j][c] * SCALE;
                    if (col > r || mk[lcol] == 0) v = -1e30f;
                    s[j][c] = v;
                    if (c < 2) mxA = fmaxf(mxA, v); else mxB = fmaxf(mxB, v);
                }
            }
            mxA = fmaxf(mxA, __shfl_xor_sync(0xffffffffu, mxA, 1));
            mxA = fmaxf(mxA, __shfl_xor_sync(0xffffffffu, mxA, 2));
            mxB = fmaxf(mxB, __shfl_xor_sync(0xffffffffu, mxB, 1));
            mxB = fmaxf(mxB, __shfl_xor_sync(0xffffffffu, mxB, 2));
            const float mnA = fmaxf(m_a, mxA), mnB = fmaxf(m_b, mxB);
            const float crA = __expf(m_a - mnA), crB = __expf(m_b - mnB);
            m_a = mnA; m_b = mnB;

            // ---- exp + row sums ----
            float smA = 0.f, smB = 0.f;
#pragma unroll
            for (int j = 0; j < 8; j++) {
#pragma unroll
                for (int c = 0; c < 4; c++) {
                    float p = __expf(s[j][c] - ((c < 2) ? mnA : mnB));
                    s[j][c] = p;
                    if (c < 2) smA += p; else smB += p;
                }
            }
            smA += __shfl_xor_sync(0xffffffffu, smA, 1);
            smA += __shfl_xor_sync(0xffffffffu, smA, 2);
            smB += __shfl_xor_sync(0xffffffffu, smB, 1);
            smB += __shfl_xor_sync(0xffffffffu, smB, 2);
            l_a = l_a * crA + smA;
            l_b = l_b * crB + smB;

            // ---- rescale O, then O += P V ----
#pragma unroll
            for (int dj = 0; dj < 16; dj++) {
                o[dj][0] *= crA; o[dj][1] *= crA;
                o[dj][2] *= crB; o[dj][3] *= crB;
            }
#pragma unroll
            for (int kk = 0; kk < 4; kk++) {
                uint32_t a[4];
                a[0] = f16x2(s[2 * kk][0],     s[2 * kk][1]);
                a[1] = f16x2(s[2 * kk][2],     s[2 * kk][3]);
                a[2] = f16x2(s[2 * kk + 1][0], s[2 * kk + 1][1]);
                a[3] = f16x2(s[2 * kk + 1][2], s[2 * kk + 1][3]);
                const uint32_t kB = (uint32_t)kk * 32;
#pragma unroll
                for (int djp = 0; djp < 8; djp++) {
                    uint32_t b0, b1, b2, b3;
                    ldsm_x4(b0, b1, b2, b3, voff[djp] + vbufB + kB);
                    mma_f16(o[2 * djp],     a, b0, b1);
                    mma_f16(o[2 * djp + 1], a, b2, b3);
                }
            }
        }

        // ---- commit staged tile into other buffer ----
        if (more) {
            uint32_t* Kd = Ksb + (buf ^ 1) * KTILE;
            __half* hV = (__half*)(Vtb + (buf ^ 1) * VTILE);
#pragma unroll
            for (int i = 0; i < 4; i++) {
                int f = tid + i * 256;
                int row = f >> 4, q = f & 15;
                *(uint4*)&Kd[row * QSTR + q * 4] = ka[i];
            }
#pragma unroll
            for (int i = 0; i < 4; i++) {
                int f = tid + i * 256;
                int row = f & 63, c8 = (f >> 6) * 8;
                const __half* pv = (const __half*)&va[i];
#pragma unroll
                for (int e = 0; e < 8; e++)
                    hV[(c8 + e) * (VSTR * 2) + row] = pv[e];
            }
            if (tid < FBN) mkb[(buf ^ 1) * FBN + tid] = mreg;
        }
        __syncthreads();
    }

    // ---- normalize + write (fp16 out) ----
    const float invA = (l_a > 0.f) ? (1.f / l_a) : 0.f;
    const float invB = (l_b > 0.f) ? (1.f / l_b) : 0.f;
    __half* rowA = O + (size_t)(b * LSEQ + m0 + wm + gid) * HID + h * HD;
    __half* rowB = rowA + (size_t)8 * HID;
#pragma unroll
    for (int dj = 0; dj < 16; dj++) {
        int cb = dj * 8 + 2 * tig;
        *(uint32_t*)(rowA + cb) = f16x2(o[dj][0] * invA, o[dj][1] * invA);
        *(uint32_t*)(rowB + cb) = f16x2(o[dj][2] * invB, o[dj][3] * invB);
    }
}

// ---------------- launch ----------------
extern "C" void kernel_launch(void* const* d_in, const int* in_sizes, int n_in,
                              void* d_out, int out_size)
{
    const float* x   = (const float*)d_in[0];
    const int* mask  = (const int*)d_in[1];
    const float* Wq  = (const float*)d_in[2];
    const float* Wk  = (const float*)d_in[3];
    const float* Wv  = (const float*)d_in[4];
    const float* Wo  = (const float*)d_in[5];
    float* out       = (float*)d_out;

    __half *xh, *wqh, *wkh, *wvh, *woh, *Qp, *Kp, *Vp, *Op;
    cudaGetSymbolAddress((void**)&xh,  g_xh);
    cudaGetSymbolAddress((void**)&wqh, g_Wqh);
    cudaGetSymbolAddress((void**)&wkh, g_Wkh);
    cudaGetSymbolAddress((void**)&wvh, g_Wvh);
    cudaGetSymbolAddress((void**)&woh, g_Woh);
    cudaGetSymbolAddress((void**)&Qp,  g_Q);
    cudaGetSymbolAddress((void**)&Kp,  g_K);
    cudaGetSymbolAddress((void**)&Vp,  g_V);
    cudaGetSymbolAddress((void**)&Op,  g_O);

    cudaFuncSetAttribute(gemm_tc<true>,  cudaFuncAttributeMaxDynamicSharedMemorySize, GEMM_SMEM);
    cudaFuncSetAttribute(gemm_tc<false>, cudaFuncAttributeMaxDynamicSharedMemorySize, GEMM_SMEM);
    cudaFuncSetAttribute(flash_tc, cudaFuncAttributeMaxDynamicSharedMemorySize, FLASH_SMEM);

    // ---- prep: convert inputs to fp16 ----
    cvt_f2h<<<(MTOT * HID / 4 + 255) / 256, 256>>>(x,  xh,  MTOT * HID / 4);
    cvt_f2h<<<(HID * HID / 4 + 255) / 256, 256>>>(Wq, wqh, HID * HID / 4);
    cvt_f2h<<<(HD * HID / 4 + 255) / 256, 256>>>(Wk, wkh, HD * HID / 4);
    cvt_f2h<<<(HD * HID / 4 + 255) / 256, 256>>>(Wv, wvh, HD * HID / 4);
    cvt_f2h<<<(HID * HID / 4 + 255) / 256, 256>>>(Wo, woh, HID * HID / 4);

    // ---- projections (fp16 out) ----
    gemm_tc<true><<<dim3(HID / TBN, MTOT / TBM), 256, GEMM_SMEM>>>(xh, wqh, Qp, HID);
    gemm_tc<true><<<dim3(HD / TBN, MTOT / TBM), 256, GEMM_SMEM>>>(xh, wkh, Kp, HD);
    gemm_tc<true><<<dim3(HD / TBN, MTOT / TBM), 256, GEMM_SMEM>>>(xh, wvh, Vp, HD);
    // ---- attention (fp16 in/out) ----
    flash_tc<<<dim3(LSEQ / FBM, BSZ * NH), 256, FLASH_SMEM>>>(Qp, Kp, Vp, mask, Op);
    // ---- output projection (f32 out) ----
    gemm_tc<false><<<dim3(HID / TBN, MTOT / TBM), 256, GEMM_SMEM>>>(Op, woh, out, HID);
}